// round 16
// baseline (speedup 1.0000x reference)
#include <cuda_runtime.h>
#include <cstdint>

// SpecialSpmmFinal: out[src[e], :] += edge_w[e, :] for e in [0, E)
// N=100000, E=3200000, F=16, fp32. src = edge[0] (first E ints of [2,E]).
//
// R15 (= R14 retry after infra failure, hardened): single fused kernel.
// Blocks 0..ZB-1 zero the output (8KB slice each) and release a global
// counter; all blocks front-batch their (zero-independent) loads, acquire-
// spin on the counter, then fire lane-transposed fire-and-forget REDs
// (thread -> 2 quarter-pieces; a warp's RED.128 covers 8 nodes x 64B).
// Counters self-reset (completion count) -> deterministic across graph
// replays; no allocations; gate is deadlock-free (all ZB zeroing blocks are
// wave-1 resident: ZB=782 < ~1184 resident blocks, bid-ordered placement).

#define N_NODES 100000
#define N_EDGES 3200000
#define FEAT 16
#define NQUARTERS (N_EDGES * 4)       // 12,800,000 quarter-rows
#define HALFQ (NQUARTERS / 2)         // 6,400,000
#define THREADS 256
#define GRID ((HALFQ + THREADS - 1) / THREADS)   // 25000
#define OUT4 (N_NODES * FEAT / 4)     // 400,000 float4
#define ZB 782                        // zeroing blocks (all inside wave 1)
#define Z_PER_BLOCK 512               // 782*512 = 400,384 >= 400,000

__device__ unsigned int g_zero_done;  // zero at module load; self-resetting
__device__ unsigned int g_finish;

// ---------------------------------------------------------------------------
// Fire-and-forget 16B float reduction (no "memory" clobber: dest is never
// read in this kernel; nothing may serialize against it).
// ---------------------------------------------------------------------------
__device__ __forceinline__ void red_add_v4(float* dst, float4 v) {
    asm volatile(
        "red.global.add.v4.f32 [%0], {%1, %2, %3, %4};"
        :: "l"(dst), "f"(v.x), "f"(v.y), "f"(v.z), "f"(v.w));
}

// Evict-first 128-bit load (edge_w is touch-once; keep out[] hot in L2).
__device__ __forceinline__ float4 ldcs4(const float4* p) {
    float4 v;
    asm volatile("ld.global.cs.v4.f32 {%0, %1, %2, %3}, [%4];"
                 : "=f"(v.x), "=f"(v.y), "=f"(v.z), "=f"(v.w)
                 : "l"(p));
    return v;
}

__device__ __forceinline__ unsigned int ld_acquire_u32(const unsigned int* p) {
    unsigned int v;
    asm volatile("ld.global.acquire.gpu.u32 %0, [%1];" : "=r"(v) : "l"(p));
    return v;
}

__device__ __forceinline__ void st_release_u32(unsigned int* p, unsigned int v) {
    asm volatile("st.global.release.gpu.u32 [%0], %1;" :: "l"(p), "r"(v));
}

// ---------------------------------------------------------------------------
// Fused zero + lane-transposed scatter-add.
// ---------------------------------------------------------------------------
__global__ void __launch_bounds__(THREADS)
fused_scatter_kernel(const int* __restrict__ src,
                     const float4* __restrict__ w,   // [E*4] float4 view
                     float* __restrict__ out) {      // [N,16] f32
    const int bid = blockIdx.x;
    const int t   = bid * THREADS + threadIdx.x;

    // ---- Phase 1: zeroing blocks clear their slice, then release. --------
    if (bid < ZB) {
        float4* out4 = (float4*)out;
        int base = bid * Z_PER_BLOCK;
        #pragma unroll
        for (int k = 0; k < Z_PER_BLOCK / THREADS; ++k) {   // 2 iters
            int i = base + k * THREADS + threadIdx.x;
            if (i < OUT4) out4[i] = make_float4(0.f, 0.f, 0.f, 0.f);
        }
        __syncthreads();
        if (threadIdx.x == 0) {
            __threadfence();                      // release the zeros
            atomicAdd(&g_zero_done, 1u);
        }
    }

    // ---- Phase 2: front-batch loads (independent of zeroing). ------------
    const bool active = (t < HALFQ);
    const int q0 = t;
    const int q1 = t + HALFQ;
    int s0 = 0, s1 = 0;
    float4 v0 = make_float4(0.f, 0.f, 0.f, 0.f);
    float4 v1 = v0;
    if (active) {
        s0 = src[q0 >> 2];
        s1 = src[q1 >> 2];
        v0 = ldcs4(w + q0);
        v1 = ldcs4(w + q1);
    }

    // ---- Phase 3: acquire-gate on zero completion (thread 0 polls). ------
    if (threadIdx.x == 0) {
        unsigned int backoff = 32;
        while (ld_acquire_u32(&g_zero_done) < ZB) {
            __nanosleep(backoff);
            if (backoff < 1024) backoff <<= 1;
        }
    }
    __syncthreads();

    // ---- Phase 4: fire-and-forget atomics. -------------------------------
    if (active) {
        red_add_v4(out + (size_t)s0 * FEAT + (q0 & 3) * 4, v0);
        red_add_v4(out + (size_t)s1 * FEAT + (q1 & 3) * 4, v1);
    }

    // ---- Phase 5: completion count; last block resets both counters. ----
    if (threadIdx.x == 0) {
        unsigned int f = atomicAdd(&g_finish, 1u);
        if (f == (unsigned int)(GRID - 1)) {
            // All blocks have passed the gate (phase 3) before incrementing
            // g_finish, so none can still observe these counters this launch.
            g_zero_done = 0u;
            st_release_u32(&g_finish, 0u);
        }
    }
}

// ---------------------------------------------------------------------------
// kernel_launch
// Inputs (metadata order): edge [2,E] int32, edge_w [E,16] f32, then scalars.
// ---------------------------------------------------------------------------
extern "C" void kernel_launch(void* const* d_in, const int* in_sizes, int n_in,
                              void* d_out, int out_size) {
    const int*    src    = (const int*)d_in[0];     // edge[0] = first E ints
    const float4* edge_w = (const float4*)d_in[1];
    float*        out    = (float*)d_out;

    (void)in_sizes; (void)n_in; (void)out_size;

    fused_scatter_kernel<<<GRID, THREADS>>>(src, edge_w, out);
}